// round 8
// baseline (speedup 1.0000x reference)
#include <cuda_runtime.h>

#define DINL __device__ __forceinline__
typedef unsigned long long ull;
#define FULLM 0xffffffffu

constexpr int V   = 32000;
constexpr int C   = 64;
constexpr int H   = 4;
constexpr int S   = 16;
constexpr int T   = 128;
constexpr int B   = 2;
constexpr int HID = 256;
constexpr int NPE = 4;
constexpr int BT  = B * T;     // 256
constexpr int D4  = 4 * C;     // 256

// ---------------- scratch (device globals; no malloc allowed) ----------------
__device__ float g_x   [BT * C];
__device__ float g_xn  [BT * C];
__device__ float g_pos [NPE * T * C];
__device__ float g_Qh  [H * B * T * D4];   // 0.5*(Qp + b1), [hb][t][d]
__device__ float g_KhT [H * B * D4 * T];   // 0.5*Kp, transposed [hb][d][t]
__device__ float g_v   [H * B * T * S];    // [hb][t][s]
__device__ float g_o   [BT * C];

DINL float sigmoidf_(float x) { return 1.0f / (1.0f + __expf(-x)); }

// packed f32x2 helpers (Blackwell: fma.rn.f32x2)
DINL ull fma2_(ull a, ull b, ull c) {
    ull r;
    asm("fma.rn.f32x2 %0, %1, %2, %3;" : "=l"(r) : "l"(a), "l"(b), "l"(c));
    return r;
}
DINL ull pack2_(float v) {
    ull r; unsigned u = __float_as_uint(v);
    asm("mov.b64 %0, {%1, %2};" : "=l"(r) : "r"(u), "r"(u));
    return r;
}
DINL ull packlh_(float lo, float hi) {
    ull r;
    asm("mov.b64 %0, {%1, %2};" : "=l"(r) : "r"(__float_as_uint(lo)), "r"(__float_as_uint(hi)));
    return r;
}
DINL void unpack2_(ull v, float& lo, float& hi) {
    unsigned a, b;
    asm("mov.b64 {%0, %1}, %2;" : "=r"(a), "=r"(b) : "l"(v));
    lo = __uint_as_float(a); hi = __uint_as_float(b);
}
DINL float wsum32_(float v) {
#pragma unroll
    for (int off = 16; off; off >>= 1) v += __shfl_xor_sync(FULLM, v, off);
    return v;
}

// block-wide sum over exactly 64 threads
DINL float bsum64(float v, float* sb, int tid) {
    sb[tid] = v; __syncthreads();
#pragma unroll
    for (int off = 32; off; off >>= 1) {
        if (tid < off) sb[tid] += sb[tid + off];
        __syncthreads();
    }
    float r = sb[0]; __syncthreads();
    return r;
}

// ---------------- K0: positional embeddings (4 tables, table->FFN->LN) -------
__global__ void k_pos(const float* __restrict__ tab,
                      const float* __restrict__ W1, const float* __restrict__ b1,
                      const float* __restrict__ W2, const float* __restrict__ b2,
                      const float* __restrict__ lg, const float* __restrict__ lb) {
    int p = blockIdx.x, t = blockIdx.y, c = threadIdx.x;
    __shared__ float pe[64], hh[64], sb[64];
    pe[c] = tab[(p * T + t) * C + c];
    __syncthreads();
    float a = b1[p * C + c];
    const float* w1 = W1 + p * C * C;
#pragma unroll 8
    for (int k = 0; k < C; k++) a = fmaf(pe[k], w1[k * C + c], a);
    hh[c] = sigmoidf_(a);
    __syncthreads();
    float y = b2[p * C + c];
    const float* w2 = W2 + p * C * C;
#pragma unroll 8
    for (int k = 0; k < C; k++) y = fmaf(hh[k], w2[k * C + c], y);
    float m = bsum64(y, sb, c) * (1.f / C);
    float d = y - m;
    float var = bsum64(d * d, sb, c) * (1.f / C);
    g_pos[(p * T + t) * C + c] = d * rsqrtf(var + 1e-5f) * lg[p * C + c] + lb[p * C + c];
}

// ---------------- K1: embed gather + ln1 + v projection (first iter only) ----
__global__ void k_embln(const int* __restrict__ idxp, const float* __restrict__ tok,
                        const float* __restrict__ g1, const float* __restrict__ b1,
                        const float* __restrict__ valW) {
    int row = blockIdx.x, c = threadIdx.x;
    int b = row >> 7, t = row & 127;
    __shared__ float xs[64], sb[64];
    float x = tok[idxp[row] * C + c];
    g_x[row * C + c] = x;
    float m = bsum64(x, sb, c) * (1.f / C);
    float d = x - m;
    float var = bsum64(d * d, sb, c) * (1.f / C);
    float xn = d * rsqrtf(var + 1e-5f) * g1[c] + b1[c];
    g_xn[row * C + c] = xn;
    xs[c] = xn;
    __syncthreads();
    int h = c >> 4, s = c & 15;
    float a = 0.f;
    const float* w = valW + h * C * S + s;
#pragma unroll 8
    for (int k = 0; k < C; k++) a = fmaf(xs[k], w[k * S], a);
    g_v[((h * B + b) * T + t) * S + s] = a;
}

// ---------------- K2: Q/K projections, chunked register loads, f32x2 ---------
// grid (T/16, H*B, 4 d-quarters), block 64 (one thread per d within quarter)
__global__ void __launch_bounds__(64) k_qk(const float* __restrict__ W1,
                                           const float* __restrict__ b1, int p) {
    int dq = blockIdx.z;
    int hb = blockIdx.y;
    int h = hb >> 1, b = hb & 1;
    int t0 = blockIdx.x * 16;
    int tid = threadIdx.x;              // 0..63
    int d = dq * 64 + tid;

    __shared__ float xs[128][18];       // [c][tt], 16 tokens, 8B-aligned rows

    for (int idx = tid; idx < 128 * 16; idx += 64) {
        int c = idx & 127, tt = idx >> 7;
        xs[c][tt] = (c < 64) ? g_pos[(p * T + t0 + tt) * C + c]
                             : g_xn[(b * T + t0 + tt) * C + (c - 64)];
    }
    __syncthreads();

    ull ak2[8], aq2[8];
    ull bq2 = pack2_(0.5f * b1[h * D4 + d]);
#pragma unroll
    for (int u = 0; u < 8; u++) { ak2[u] = 0ULL; aq2[u] = bq2; }

    const float* Wk = W1 + h * D4 * D4 + d;   // rows [0,128): key half
    const float* Wq = Wk + 128 * D4;          // rows [128,256): query half

    for (int c0 = 0; c0 < 128; c0 += 16) {
        float wk[16], wq[16];
#pragma unroll
        for (int u = 0; u < 16; u++) {
            wk[u] = Wk[(c0 + u) * D4];
            wq[u] = Wq[(c0 + u) * D4];
        }
#pragma unroll
        for (int cc = 0; cc < 16; cc++) {
            ull wk2 = pack2_(0.5f * wk[cc]);
            ull wq2 = pack2_(0.5f * wq[cc]);
            const ull* xp = reinterpret_cast<const ull*>(&xs[c0 + cc][0]);
#pragma unroll
            for (int u = 0; u < 8; u++) {
                ull xv = xp[u];
                ak2[u] = fma2_(xv, wk2, ak2[u]);
                aq2[u] = fma2_(xv, wq2, aq2[u]);
            }
        }
    }

    // K transposed: thread owns row d, writes 16 consecutive t as 8B pairs
    float* kout = &g_KhT[(hb * D4 + d) * T + t0];
#pragma unroll
    for (int u = 0; u < 8; u++)
        *reinterpret_cast<ull*>(&kout[2 * u]) = ak2[u];
    // Q: scatter per t (coalesced across tid)
#pragma unroll
    for (int u = 0; u < 8; u++) {
        float lo, hi; unpack2_(aq2[u], lo, hi);
        g_Qh[(hb * T + t0 + 2 * u) * D4 + d]     = lo;
        g_Qh[(hb * T + t0 + 2 * u + 1) * D4 + d] = hi;
    }
}

// ---------------- K3: tiled attention: 8 queries/block, d split over 2 halves -
// grid (T/8, H*B), block 256: tid = dh*128 + j
__global__ void __launch_bounds__(256) k_attn(const float* __restrict__ W2a) {
    int it = blockIdx.x, hb = blockIdx.y;
    int h = hb >> 1, b = hb & 1;
    int i0 = it * 8;
    int tid = threadIdx.x;
    int j = tid & 127, dh = tid >> 7;

    __shared__ float qs[8][260];
    __shared__ float w2s[256];
    __shared__ float vs[128][17];
    __shared__ float wei[8][132];
    __shared__ float ps[8][132];

    for (int idx = tid; idx < 8 * 256; idx += 256) {
        int ii = idx >> 8, d = idx & 255;
        qs[ii][d] = g_Qh[(hb * T + i0 + ii) * D4 + d];
    }
    w2s[tid] = 0.5f * W2a[h * D4 + tid];
    int vrows = i0 + 8;
    for (int idx = tid; idx < vrows * 16; idx += 256) {
        int jr = idx >> 4, s = idx & 15;
        vs[jr][s] = g_v[(hb * T + jr) * S + s];
    }
    __syncthreads();

    float acc[8];
#pragma unroll
    for (int ii = 0; ii < 8; ii++) acc[ii] = 0.f;
    if (j < i0 + 8) {
        const float* Kc = g_KhT + (hb * D4 + dh * 128) * T + j;
        const float* w2p = &w2s[dh * 128];
        const float* qp0 = &qs[0][dh * 128];
        for (int d0 = 0; d0 < 128; d0 += 8) {
            float kb[8];
#pragma unroll
            for (int u = 0; u < 8; u++) kb[u] = Kc[(d0 + u) * T];
#pragma unroll
            for (int u = 0; u < 8; u++) {
                float w2d = w2p[d0 + u];
#pragma unroll
                for (int ii = 0; ii < 8; ii++) {
                    float th;
                    asm("tanh.approx.f32 %0, %1;"
                        : "=f"(th) : "f"(qp0[ii * 260 + d0 + u] + kb[u]));
                    acc[ii] = fmaf(w2d, th, acc[ii]);
                }
            }
        }
    }
    if (dh == 1) {
#pragma unroll
        for (int ii = 0; ii < 8; ii++) ps[ii][j] = acc[ii];
    }
    __syncthreads();
    if (dh == 0) {
#pragma unroll
        for (int ii = 0; ii < 8; ii++)
            wei[ii][j] = (j <= i0 + ii) ? (acc[ii] + ps[ii][j]) * 0.125f : -1e30f;
    }
    __syncthreads();
    // softmax: warp w handles row w (8 warps)
    int wd = tid >> 5, lane = tid & 31;
    {
        float v0 = wei[wd][lane],      v1 = wei[wd][lane + 32];
        float v2 = wei[wd][lane + 64], v3 = wei[wd][lane + 96];
        float mx = fmaxf(fmaxf(v0, v1), fmaxf(v2, v3));
#pragma unroll
        for (int off = 16; off; off >>= 1) mx = fmaxf(mx, __shfl_xor_sync(FULLM, mx, off));
        float e0 = __expf(v0 - mx), e1 = __expf(v1 - mx);
        float e2 = __expf(v2 - mx), e3 = __expf(v3 - mx);
        float s = e0 + e1 + e2 + e3;
#pragma unroll
        for (int off = 16; off; off >>= 1) s += __shfl_xor_sync(FULLM, s, off);
        float inv = __fdividef(1.f, s);
        wei[wd][lane] = e0 * inv;      wei[wd][lane + 32] = e1 * inv;
        wei[wd][lane + 64] = e2 * inv; wei[wd][lane + 96] = e3 * inv;
    }
    __syncthreads();
    // o: thread (tid&127) owns (ii, s); j-sum split over dh halves
    int ii = (tid & 127) >> 4, s = tid & 15;
    int lo = dh * 64;
    int hiend = min(i0 + ii, dh * 64 + 63);
    float o = 0.f;
    for (int jr = lo; jr <= hiend; jr++) o = fmaf(wei[ii][jr], vs[jr][s], o);
    if (dh == 1) ps[ii][s] = o;
    __syncthreads();
    if (dh == 0)
        g_o[(b * T + i0 + ii) * C + h * S + s] = o + ps[ii][s];
}

// ---------------- K4: warp-per-row proj+ln2+FFN+ln3, fused ln1+v --------------
// grid(BT/2) x 64 threads: each warp owns one row; no __syncthreads.
__global__ void __launch_bounds__(64) k_mlp(
        const float* __restrict__ pW, const float* __restrict__ pb,
        const float* __restrict__ g2, const float* __restrict__ b2,
        const float* __restrict__ fW1, const float* __restrict__ fb1,
        const float* __restrict__ fW2, const float* __restrict__ fb2,
        const float* __restrict__ g3, const float* __restrict__ b3,
        const float* __restrict__ g1, const float* __restrict__ b1,
        const float* __restrict__ valW) {
    int w = threadIdx.x >> 5, lam = threadIdx.x & 31;
    int row = blockIdx.x * 2 + w;
    int b = row >> 7, t = row & 127;
    __shared__ ull hs2[2][256];

    float2 o2 = reinterpret_cast<const float2*>(g_o)[row * 32 + lam];
    float2 x2 = reinterpret_cast<const float2*>(g_x)[row * 32 + lam];
    float2 pb2 = reinterpret_cast<const float2*>(pb)[lam];

    // proj + residual: acc = x + pb + o @ pW
    ull acc = packlh_(x2.x + pb2.x, x2.y + pb2.y);
    const ull* pW2 = reinterpret_cast<const ull*>(pW);
#pragma unroll 4
    for (int kp = 0; kp < 32; kp++) {
        float ox = __shfl_sync(FULLM, o2.x, kp);
        float oy = __shfl_sync(FULLM, o2.y, kp);
        ull w0 = pW2[(2 * kp) * 32 + lam];
        ull w1 = pW2[(2 * kp + 1) * 32 + lam];
        acc = fma2_(pack2_(ox), w0, acc);
        acc = fma2_(pack2_(oy), w1, acc);
    }
    float xv0, xv1; unpack2_(acc, xv0, xv1);

    // ln2
    float m = wsum32_(xv0 + xv1) * (1.f / C);
    float d0 = xv0 - m, d1 = xv1 - m;
    float var = wsum32_(d0 * d0 + d1 * d1) * (1.f / C);
    float rstd = rsqrtf(var + 1e-5f);
    float2 g2v = reinterpret_cast<const float2*>(g2)[lam];
    float2 b2v = reinterpret_cast<const float2*>(b2)[lam];
    float xn0 = d0 * rstd * g2v.x + b2v.x;
    float xn1 = d1 * rstd * g2v.y + b2v.y;

    // FFN1: lane owns hid [8*lam, 8*lam+8)
    ull a4[4];
    const ull* fb1u = reinterpret_cast<const ull*>(fb1);
#pragma unroll
    for (int u = 0; u < 4; u++) a4[u] = fb1u[lam * 4 + u];
#pragma unroll 4
    for (int kp = 0; kp < 32; kp++) {
        float k0v = __shfl_sync(FULLM, xn0, kp);
        float k1v = __shfl_sync(FULLM, xn1, kp);
        const ull* r0 = reinterpret_cast<const ull*>(fW1 + (2 * kp) * HID) + lam * 4;
        const ull* r1 = r0 + HID / 2;
        ull p0 = pack2_(k0v), p1 = pack2_(k1v);
#pragma unroll
        for (int u = 0; u < 4; u++) {
            a4[u] = fma2_(p0, r0[u], a4[u]);
            a4[u] = fma2_(p1, r1[u], a4[u]);
        }
    }
#pragma unroll
    for (int u = 0; u < 4; u++) {
        float lo, hi; unpack2_(a4[u], lo, hi);
        hs2[w][8 * lam + 2 * u]     = pack2_(sigmoidf_(lo));
        hs2[w][8 * lam + 2 * u + 1] = pack2_(sigmoidf_(hi));
    }
    __syncwarp();

    // FFN2 + residual
    float2 fb2v = reinterpret_cast<const float2*>(fb2)[lam];
    ull accy = packlh_(xv0 + fb2v.x, xv1 + fb2v.y);
    const ull* fW2u = reinterpret_cast<const ull*>(fW2);
#pragma unroll 8
    for (int k = 0; k < HID; k++)
        accy = fma2_(hs2[w][k], fW2u[k * 32 + lam], accy);
    float y0, y1; unpack2_(accy, y0, y1);

    // ln3 -> block output
    m = wsum32_(y0 + y1) * (1.f / C);
    d0 = y0 - m; d1 = y1 - m;
    var = wsum32_(d0 * d0 + d1 * d1) * (1.f / C);
    rstd = rsqrtf(var + 1e-5f);
    float2 g3v = reinterpret_cast<const float2*>(g3)[lam];
    float2 b3v = reinterpret_cast<const float2*>(b3)[lam];
    float z0 = d0 * rstd * g3v.x + b3v.x;
    float z1 = d1 * rstd * g3v.y + b3v.y;
    reinterpret_cast<float2*>(g_x)[row * 32 + lam] = make_float2(z0, z1);

    // fused ln1 for next layer
    m = wsum32_(z0 + z1) * (1.f / C);
    d0 = z0 - m; d1 = z1 - m;
    var = wsum32_(d0 * d0 + d1 * d1) * (1.f / C);
    rstd = rsqrtf(var + 1e-5f);
    float2 g1v = reinterpret_cast<const float2*>(g1)[lam];
    float2 b1v = reinterpret_cast<const float2*>(b1)[lam];
    float q0 = d0 * rstd * g1v.x + b1v.x;
    float q1 = d1 * rstd * g1v.y + b1v.y;
    reinterpret_cast<float2*>(g_xn)[row * 32 + lam] = make_float2(q0, q1);

    // fused v projection: lane owns out pair c=(2lam, 2lam+1) -> h=lam>>3
    int hv = lam >> 3, sp = lam & 7;
    const ull* vwb = reinterpret_cast<const ull*>(valW) + hv * 512 + sp;
    ull accv = 0ULL;
#pragma unroll 4
    for (int kp = 0; kp < 32; kp++) {
        float k0v = __shfl_sync(FULLM, q0, kp);
        float k1v = __shfl_sync(FULLM, q1, kp);
        ull w0 = vwb[kp * 16];
        ull w1 = vwb[kp * 16 + 8];
        accv = fma2_(pack2_(k0v), w0, accv);
        accv = fma2_(pack2_(k1v), w1, accv);
    }
    reinterpret_cast<ull*>(g_v)[((hv * B + b) * T + t) * 8 + sp] = accv;
}

// ---------------- K5: lm_head, 4 vocab/thread, f32x2 --------------------------
// grid (V/256, BT/32), block 64; thread owns 2 vocab pairs, 32 rows.
__global__ void __launch_bounds__(64) k_lm(const float* __restrict__ W,
                                           const float* __restrict__ bias,
                                           float* __restrict__ out) {
    int vt = blockIdx.x, rt = blockIdx.y;
    int vv = vt * 256 + threadIdx.x * 4;
    __shared__ alignas(16) float xs[32][68];
    for (int idx = threadIdx.x; idx < 32 * 64; idx += 64) {
        int r = idx >> 6, cc = idx & 63;
        xs[r][cc] = g_x[(rt * 32 + r) * C + cc];
    }
    ulonglong2 bb = *reinterpret_cast<const ulonglong2*>(bias + vv);
    ull acc[32][2];
#pragma unroll
    for (int r = 0; r < 32; r++) { acc[r][0] = bb.x; acc[r][1] = bb.y; }
    __syncthreads();
    for (int cb = 0; cb < 64; cb += 4) {
        const ulonglong2 w0 = *reinterpret_cast<const ulonglong2*>(W + (size_t)(cb + 0) * V + vv);
        const ulonglong2 w1 = *reinterpret_cast<const ulonglong2*>(W + (size_t)(cb + 1) * V + vv);
        const ulonglong2 w2 = *reinterpret_cast<const ulonglong2*>(W + (size_t)(cb + 2) * V + vv);
        const ulonglong2 w3 = *reinterpret_cast<const ulonglong2*>(W + (size_t)(cb + 3) * V + vv);
#pragma unroll
        for (int r = 0; r < 32; r++) {
            const float4 xq = *reinterpret_cast<const float4*>(&xs[r][cb]);
            ull px;
            px = pack2_(xq.x); acc[r][0] = fma2_(w0.x, px, acc[r][0]); acc[r][1] = fma2_(w0.y, px, acc[r][1]);
            px = pack2_(xq.y); acc[r][0] = fma2_(w1.x, px, acc[r][0]); acc[r][1] = fma2_(w1.y, px, acc[r][1]);
            px = pack2_(xq.z); acc[r][0] = fma2_(w2.x, px, acc[r][0]); acc[r][1] = fma2_(w2.y, px, acc[r][1]);
            px = pack2_(xq.w); acc[r][0] = fma2_(w3.x, px, acc[r][0]); acc[r][1] = fma2_(w3.y, px, acc[r][1]);
        }
    }
#pragma unroll
    for (int r = 0; r < 32; r++) {
        ulonglong2 o2; o2.x = acc[r][0]; o2.y = acc[r][1];
        *reinterpret_cast<ulonglong2*>(out + (size_t)(rt * 32 + r) * V + vv) = o2;
    }
}

// ---------------- launch -------------------------------------------------------
extern "C" void kernel_launch(void* const* d_in, const int* in_sizes, int n_in,
                              void* d_out, int out_size) {
    (void)in_sizes; (void)n_in; (void)out_size;
    const int*   idx      = (const int*)  d_in[0];
    const float* tok_emb  = (const float*)d_in[1];
    const float* pe_tab   = (const float*)d_in[2];
    const float* pe_W1    = (const float*)d_in[3];
    const float* pe_b1    = (const float*)d_in[4];
    const float* pe_W2    = (const float*)d_in[5];
    const float* pe_b2    = (const float*)d_in[6];
    const float* pe_lg    = (const float*)d_in[7];
    const float* pe_lb    = (const float*)d_in[8];
    const float* ln1_g    = (const float*)d_in[9];
    const float* ln1_b    = (const float*)d_in[10];
    const float* att_W1   = (const float*)d_in[11];
    const float* att_b1   = (const float*)d_in[12];
    const float* att_W2   = (const float*)d_in[13];
    /* att_b2 = d_in[14] — constant over j, cancels in softmax */
    const float* val_W    = (const float*)d_in[15];
    const float* proj_W   = (const float*)d_in[16];
    const float* proj_b   = (const float*)d_in[17];
    const float* ln2_g    = (const float*)d_in[18];
    const float* ln2_b    = (const float*)d_in[19];
    const float* ff_W1    = (const float*)d_in[20];
    const float* ff_b1    = (const float*)d_in[21];
    const float* ff_W2    = (const float*)d_in[22];
    const float* ff_b2    = (const float*)d_in[23];
    const float* ln3_g    = (const float*)d_in[24];
    const float* ln3_b    = (const float*)d_in[25];
    const float* lm_W     = (const float*)d_in[26];
    const float* lm_b     = (const float*)d_in[27];
    float* out = (float*)d_out;

    k_pos<<<dim3(NPE, T), 64>>>(pe_tab, pe_W1, pe_b1, pe_W2, pe_b2, pe_lg, pe_lb);
    k_embln<<<BT, 64>>>(idx, tok_emb, ln1_g, ln1_b, val_W);
    for (int p = 0; p < NPE; p++) {
        k_qk  <<<dim3(T / 16, H * B, 4), 64>>>(att_W1, att_b1, p);
        k_attn<<<dim3(T / 8, H * B), 256>>>(att_W2);
        k_mlp <<<BT / 2, 64>>>(proj_W, proj_b, ln2_g, ln2_b,
                               ff_W1, ff_b1, ff_W2, ff_b2, ln3_g, ln3_b,
                               ln1_g, ln1_b, val_W);
    }
    k_lm<<<dim3(V / 256, BT / 32), 64>>>(lm_W, lm_b, out);
}

// round 9
// speedup vs baseline: 1.1222x; 1.1222x over previous
#include <cuda_runtime.h>

#define DINL __device__ __forceinline__
typedef unsigned long long ull;
#define FULLM 0xffffffffu

constexpr int V   = 32000;
constexpr int C   = 64;
constexpr int H   = 4;
constexpr int S   = 16;
constexpr int T   = 128;
constexpr int B   = 2;
constexpr int HID = 256;
constexpr int NPE = 4;
constexpr int BT  = B * T;     // 256
constexpr int D4  = 4 * C;     // 256

// ---------------- scratch (device globals; no malloc allowed) ----------------
__device__ float g_x   [BT * C];
__device__ float g_xn  [BT * C];
__device__ float g_pos [NPE * T * C];
__device__ float g_Qh  [H * B * T * D4];   // 0.5*(Qp + b1), [hb][t][d]
__device__ float g_KhT [H * B * D4 * T];   // 0.5*Kp, transposed [hb][d][t]
__device__ float g_v   [H * B * T * S];    // [hb][t][s]
__device__ float g_o   [BT * C];

DINL float sigmoidf_(float x) { return 1.0f / (1.0f + __expf(-x)); }

// packed f32x2 helpers (Blackwell: fma.rn.f32x2)
DINL ull fma2_(ull a, ull b, ull c) {
    ull r;
    asm("fma.rn.f32x2 %0, %1, %2, %3;" : "=l"(r) : "l"(a), "l"(b), "l"(c));
    return r;
}
DINL ull pack2_(float v) {
    ull r; unsigned u = __float_as_uint(v);
    asm("mov.b64 %0, {%1, %2};" : "=l"(r) : "r"(u), "r"(u));
    return r;
}
DINL ull packlh_(float lo, float hi) {
    ull r;
    asm("mov.b64 %0, {%1, %2};" : "=l"(r) : "r"(__float_as_uint(lo)), "r"(__float_as_uint(hi)));
    return r;
}
DINL void unpack2_(ull v, float& lo, float& hi) {
    unsigned a, b;
    asm("mov.b64 {%0, %1}, %2;" : "=r"(a), "=r"(b) : "l"(v));
    lo = __uint_as_float(a); hi = __uint_as_float(b);
}
DINL float wsum32_(float v) {
#pragma unroll
    for (int off = 16; off; off >>= 1) v += __shfl_xor_sync(FULLM, v, off);
    return v;
}

// block-wide sum over exactly 64 threads
DINL float bsum64(float v, float* sb, int tid) {
    sb[tid] = v; __syncthreads();
#pragma unroll
    for (int off = 32; off; off >>= 1) {
        if (tid < off) sb[tid] += sb[tid + off];
        __syncthreads();
    }
    float r = sb[0]; __syncthreads();
    return r;
}

// ---------------- K0: positional embeddings (4 tables, table->FFN->LN) -------
__global__ void k_pos(const float* __restrict__ tab,
                      const float* __restrict__ W1, const float* __restrict__ b1,
                      const float* __restrict__ W2, const float* __restrict__ b2,
                      const float* __restrict__ lg, const float* __restrict__ lb) {
    int p = blockIdx.x, t = blockIdx.y, c = threadIdx.x;
    __shared__ float pe[64], hh[64], sb[64];
    pe[c] = tab[(p * T + t) * C + c];
    __syncthreads();
    float a = b1[p * C + c];
    const float* w1 = W1 + p * C * C;
#pragma unroll 8
    for (int k = 0; k < C; k++) a = fmaf(pe[k], w1[k * C + c], a);
    hh[c] = sigmoidf_(a);
    __syncthreads();
    float y = b2[p * C + c];
    const float* w2 = W2 + p * C * C;
#pragma unroll 8
    for (int k = 0; k < C; k++) y = fmaf(hh[k], w2[k * C + c], y);
    float m = bsum64(y, sb, c) * (1.f / C);
    float d = y - m;
    float var = bsum64(d * d, sb, c) * (1.f / C);
    g_pos[(p * T + t) * C + c] = d * rsqrtf(var + 1e-5f) * lg[p * C + c] + lb[p * C + c];
}

// ---------------- K1: embed gather + ln1 + v projection (first iter only) ----
__global__ void k_embln(const int* __restrict__ idxp, const float* __restrict__ tok,
                        const float* __restrict__ g1, const float* __restrict__ b1,
                        const float* __restrict__ valW) {
    int row = blockIdx.x, c = threadIdx.x;
    int b = row >> 7, t = row & 127;
    __shared__ float xs[64], sb[64];
    float x = tok[idxp[row] * C + c];
    g_x[row * C + c] = x;
    float m = bsum64(x, sb, c) * (1.f / C);
    float d = x - m;
    float var = bsum64(d * d, sb, c) * (1.f / C);
    float xn = d * rsqrtf(var + 1e-5f) * g1[c] + b1[c];
    g_xn[row * C + c] = xn;
    xs[c] = xn;
    __syncthreads();
    int h = c >> 4, s = c & 15;
    float a = 0.f;
    const float* w = valW + h * C * S + s;
#pragma unroll 8
    for (int k = 0; k < C; k++) a = fmaf(xs[k], w[k * S], a);
    g_v[((h * B + b) * T + t) * S + s] = a;
}

// ---------------- K2: Q/K projections, chunked register loads, f32x2 ---------
// grid (T/16, H*B, 4 d-quarters), block 64 (one thread per d within quarter)
__global__ void __launch_bounds__(64) k_qk(const float* __restrict__ W1,
                                           const float* __restrict__ b1, int p) {
    int dq = blockIdx.z;
    int hb = blockIdx.y;
    int h = hb >> 1, b = hb & 1;
    int t0 = blockIdx.x * 16;
    int tid = threadIdx.x;              // 0..63
    int d = dq * 64 + tid;

    __shared__ float xs[128][18];       // [c][tt], 16 tokens, 8B-aligned rows

    for (int idx = tid; idx < 128 * 16; idx += 64) {
        int c = idx & 127, tt = idx >> 7;
        xs[c][tt] = (c < 64) ? g_pos[(p * T + t0 + tt) * C + c]
                             : g_xn[(b * T + t0 + tt) * C + (c - 64)];
    }
    __syncthreads();

    ull ak2[8], aq2[8];
    ull bq2 = pack2_(0.5f * b1[h * D4 + d]);
#pragma unroll
    for (int u = 0; u < 8; u++) { ak2[u] = 0ULL; aq2[u] = bq2; }

    const float* Wk = W1 + h * D4 * D4 + d;   // rows [0,128): key half
    const float* Wq = Wk + 128 * D4;          // rows [128,256): query half

    for (int c0 = 0; c0 < 128; c0 += 16) {
        float wk[16], wq[16];
#pragma unroll
        for (int u = 0; u < 16; u++) {
            wk[u] = Wk[(c0 + u) * D4];
            wq[u] = Wq[(c0 + u) * D4];
        }
#pragma unroll
        for (int cc = 0; cc < 16; cc++) {
            ull wk2 = pack2_(0.5f * wk[cc]);
            ull wq2 = pack2_(0.5f * wq[cc]);
            const ull* xp = reinterpret_cast<const ull*>(&xs[c0 + cc][0]);
#pragma unroll
            for (int u = 0; u < 8; u++) {
                ull xv = xp[u];
                ak2[u] = fma2_(xv, wk2, ak2[u]);
                aq2[u] = fma2_(xv, wq2, aq2[u]);
            }
        }
    }

    // K transposed: thread owns row d, writes 16 consecutive t as 8B pairs
    float* kout = &g_KhT[(hb * D4 + d) * T + t0];
#pragma unroll
    for (int u = 0; u < 8; u++)
        *reinterpret_cast<ull*>(&kout[2 * u]) = ak2[u];
    // Q: scatter per t (coalesced across tid)
#pragma unroll
    for (int u = 0; u < 8; u++) {
        float lo, hi; unpack2_(aq2[u], lo, hi);
        g_Qh[(hb * T + t0 + 2 * u) * D4 + d]     = lo;
        g_Qh[(hb * T + t0 + 2 * u + 1) * D4 + d] = hi;
    }
}

// ---------------- K3: per-query attention, d split over 2 halves --------------
// grid (T, H*B), block 256: tid = dh*128 + j; thread does 128 tanh.
__global__ void __launch_bounds__(256) k_attn(const float* __restrict__ W2a) {
    int i = blockIdx.x, hb = blockIdx.y;
    int h = hb >> 1, b = hb & 1;
    int tid = threadIdx.x;
    int j = tid & 127, dh = tid >> 7;

    __shared__ float2 qw[256];
    __shared__ float part[128];
    __shared__ float rb[128];
    __shared__ float wei[128];
    __shared__ float obuf[256];

    qw[tid] = make_float2(g_Qh[(hb * T + i) * D4 + tid],
                          0.5f * W2a[h * D4 + tid]);
    __syncthreads();

    float acc = 0.f;
    if (j <= i) {
        const float* Kc = g_KhT + (hb * D4 + dh * 128) * T + j;
        const float2* qp = qw + dh * 128;
        for (int d0 = 0; d0 < 128; d0 += 16) {
            float kb[16];
#pragma unroll
            for (int u = 0; u < 16; u++) kb[u] = Kc[(d0 + u) * T];
#pragma unroll
            for (int u = 0; u < 16; u++) {
                float2 q = qp[d0 + u];
                float th;
                asm("tanh.approx.f32 %0, %1;" : "=f"(th) : "f"(q.x + kb[u]));
                acc = fmaf(q.y, th, acc);
            }
        }
    }
    if (dh == 1) part[j] = acc;
    __syncthreads();
    if (dh == 0) {
        float sc = (j <= i) ? (acc + part[j]) * 0.125f : -1e30f;
        wei[j] = sc;
        rb[j] = sc;
    }
    __syncthreads();
    // max reduce over 128
#pragma unroll
    for (int off = 64; off; off >>= 1) {
        if (tid < off) rb[tid] = fmaxf(rb[tid], rb[tid + off]);
        __syncthreads();
    }
    float mx = rb[0];
    __syncthreads();
    if (dh == 0) rb[j] = (j <= i) ? __expf(wei[j] - mx) : 0.f;
    __syncthreads();
    if (dh == 0) wei[j] = rb[j];         // keep exp values
    // sum reduce over 128
#pragma unroll
    for (int off = 64; off; off >>= 1) {
        if (tid < off) rb[tid] += rb[tid + off];
        __syncthreads();
    }
    float inv = __fdividef(1.f, rb[0]);
    __syncthreads();

    // o[i, h*16+s] = inv * sum_j exp[j] * v[j][s]; 16 j-partitions x 16 s
    int part16 = tid >> 4, so = tid & 15;
    const float* vp = g_v + hb * T * S;
    float a = 0.f;
    for (int jj = part16; jj <= i; jj += 16) a = fmaf(wei[jj], vp[jj * S + so], a);
    obuf[part16 * 16 + so] = a;
    __syncthreads();
    if (tid < 16) {
        float o = 0.f;
#pragma unroll
        for (int k = 0; k < 16; k++) o += obuf[k * 16 + tid];
        g_o[(b * T + i) * C + h * S + tid] = o * inv;
    }
}

// ---------------- K4: warp-per-row proj+ln2+FFN+ln3, fused ln1+v --------------
// grid(BT/2) x 64 threads: each warp owns one row; no __syncthreads.
__global__ void __launch_bounds__(64) k_mlp(
        const float* __restrict__ pW, const float* __restrict__ pb,
        const float* __restrict__ g2, const float* __restrict__ b2,
        const float* __restrict__ fW1, const float* __restrict__ fb1,
        const float* __restrict__ fW2, const float* __restrict__ fb2,
        const float* __restrict__ g3, const float* __restrict__ b3,
        const float* __restrict__ g1, const float* __restrict__ b1,
        const float* __restrict__ valW) {
    int w = threadIdx.x >> 5, lam = threadIdx.x & 31;
    int row = blockIdx.x * 2 + w;
    int b = row >> 7, t = row & 127;
    __shared__ ull hs2[2][256];

    float2 o2 = reinterpret_cast<const float2*>(g_o)[row * 32 + lam];
    float2 x2 = reinterpret_cast<const float2*>(g_x)[row * 32 + lam];
    float2 pb2 = reinterpret_cast<const float2*>(pb)[lam];

    // proj + residual: acc = x + pb + o @ pW
    ull acc = packlh_(x2.x + pb2.x, x2.y + pb2.y);
    const ull* pW2 = reinterpret_cast<const ull*>(pW);
#pragma unroll 4
    for (int kp = 0; kp < 32; kp++) {
        float ox = __shfl_sync(FULLM, o2.x, kp);
        float oy = __shfl_sync(FULLM, o2.y, kp);
        ull w0 = pW2[(2 * kp) * 32 + lam];
        ull w1 = pW2[(2 * kp + 1) * 32 + lam];
        acc = fma2_(pack2_(ox), w0, acc);
        acc = fma2_(pack2_(oy), w1, acc);
    }
    float xv0, xv1; unpack2_(acc, xv0, xv1);

    // ln2
    float m = wsum32_(xv0 + xv1) * (1.f / C);
    float d0 = xv0 - m, d1 = xv1 - m;
    float var = wsum32_(d0 * d0 + d1 * d1) * (1.f / C);
    float rstd = rsqrtf(var + 1e-5f);
    float2 g2v = reinterpret_cast<const float2*>(g2)[lam];
    float2 b2v = reinterpret_cast<const float2*>(b2)[lam];
    float xn0 = d0 * rstd * g2v.x + b2v.x;
    float xn1 = d1 * rstd * g2v.y + b2v.y;

    // FFN1: lane owns hid [8*lam, 8*lam+8)
    ull a4[4];
    const ull* fb1u = reinterpret_cast<const ull*>(fb1);
#pragma unroll
    for (int u = 0; u < 4; u++) a4[u] = fb1u[lam * 4 + u];
#pragma unroll 4
    for (int kp = 0; kp < 32; kp++) {
        float k0v = __shfl_sync(FULLM, xn0, kp);
        float k1v = __shfl_sync(FULLM, xn1, kp);
        const ull* r0 = reinterpret_cast<const ull*>(fW1 + (2 * kp) * HID) + lam * 4;
        const ull* r1 = r0 + HID / 2;
        ull p0 = pack2_(k0v), p1 = pack2_(k1v);
#pragma unroll
        for (int u = 0; u < 4; u++) {
            a4[u] = fma2_(p0, r0[u], a4[u]);
            a4[u] = fma2_(p1, r1[u], a4[u]);
        }
    }
#pragma unroll
    for (int u = 0; u < 4; u++) {
        float lo, hi; unpack2_(a4[u], lo, hi);
        hs2[w][8 * lam + 2 * u]     = pack2_(sigmoidf_(lo));
        hs2[w][8 * lam + 2 * u + 1] = pack2_(sigmoidf_(hi));
    }
    __syncwarp();

    // FFN2 + residual
    float2 fb2v = reinterpret_cast<const float2*>(fb2)[lam];
    ull accy = packlh_(xv0 + fb2v.x, xv1 + fb2v.y);
    const ull* fW2u = reinterpret_cast<const ull*>(fW2);
#pragma unroll 8
    for (int k = 0; k < HID; k++)
        accy = fma2_(hs2[w][k], fW2u[k * 32 + lam], accy);
    float y0, y1; unpack2_(accy, y0, y1);

    // ln3 -> block output
    m = wsum32_(y0 + y1) * (1.f / C);
    d0 = y0 - m; d1 = y1 - m;
    var = wsum32_(d0 * d0 + d1 * d1) * (1.f / C);
    rstd = rsqrtf(var + 1e-5f);
    float2 g3v = reinterpret_cast<const float2*>(g3)[lam];
    float2 b3v = reinterpret_cast<const float2*>(b3)[lam];
    float z0 = d0 * rstd * g3v.x + b3v.x;
    float z1 = d1 * rstd * g3v.y + b3v.y;
    reinterpret_cast<float2*>(g_x)[row * 32 + lam] = make_float2(z0, z1);

    // fused ln1 for next layer
    m = wsum32_(z0 + z1) * (1.f / C);
    d0 = z0 - m; d1 = z1 - m;
    var = wsum32_(d0 * d0 + d1 * d1) * (1.f / C);
    rstd = rsqrtf(var + 1e-5f);
    float2 g1v = reinterpret_cast<const float2*>(g1)[lam];
    float2 b1v = reinterpret_cast<const float2*>(b1)[lam];
    float q0 = d0 * rstd * g1v.x + b1v.x;
    float q1 = d1 * rstd * g1v.y + b1v.y;
    reinterpret_cast<float2*>(g_xn)[row * 32 + lam] = make_float2(q0, q1);

    // fused v projection: lane owns out pair c=(2lam, 2lam+1) -> h=lam>>3
    int hv = lam >> 3, sp = lam & 7;
    const ull* vwb = reinterpret_cast<const ull*>(valW) + hv * 512 + sp;
    ull accv = 0ULL;
#pragma unroll 4
    for (int kp = 0; kp < 32; kp++) {
        float k0v = __shfl_sync(FULLM, q0, kp);
        float k1v = __shfl_sync(FULLM, q1, kp);
        ull w0 = vwb[kp * 16];
        ull w1 = vwb[kp * 16 + 8];
        accv = fma2_(pack2_(k0v), w0, accv);
        accv = fma2_(pack2_(k1v), w1, accv);
    }
    reinterpret_cast<ull*>(g_v)[((hv * B + b) * T + t) * 8 + sp] = accv;
}

// ---------------- K5: lm_head, 4 vocab/thread, f32x2 --------------------------
// grid (V/256, BT/32), block 64; thread owns 2 vocab pairs, 32 rows.
__global__ void __launch_bounds__(64) k_lm(const float* __restrict__ W,
                                           const float* __restrict__ bias,
                                           float* __restrict__ out) {
    int vt = blockIdx.x, rt = blockIdx.y;
    int vv = vt * 256 + threadIdx.x * 4;
    __shared__ alignas(16) float xs[32][68];
    for (int idx = threadIdx.x; idx < 32 * 64; idx += 64) {
        int r = idx >> 6, cc = idx & 63;
        xs[r][cc] = g_x[(rt * 32 + r) * C + cc];
    }
    ulonglong2 bb = *reinterpret_cast<const ulonglong2*>(bias + vv);
    ull acc[32][2];
#pragma unroll
    for (int r = 0; r < 32; r++) { acc[r][0] = bb.x; acc[r][1] = bb.y; }
    __syncthreads();
    for (int cb = 0; cb < 64; cb += 4) {
        const ulonglong2 w0 = *reinterpret_cast<const ulonglong2*>(W + (size_t)(cb + 0) * V + vv);
        const ulonglong2 w1 = *reinterpret_cast<const ulonglong2*>(W + (size_t)(cb + 1) * V + vv);
        const ulonglong2 w2 = *reinterpret_cast<const ulonglong2*>(W + (size_t)(cb + 2) * V + vv);
        const ulonglong2 w3 = *reinterpret_cast<const ulonglong2*>(W + (size_t)(cb + 3) * V + vv);
#pragma unroll
        for (int r = 0; r < 32; r++) {
            const float4 xq = *reinterpret_cast<const float4*>(&xs[r][cb]);
            ull px;
            px = pack2_(xq.x); acc[r][0] = fma2_(w0.x, px, acc[r][0]); acc[r][1] = fma2_(w0.y, px, acc[r][1]);
            px = pack2_(xq.y); acc[r][0] = fma2_(w1.x, px, acc[r][0]); acc[r][1] = fma2_(w1.y, px, acc[r][1]);
            px = pack2_(xq.z); acc[r][0] = fma2_(w2.x, px, acc[r][0]); acc[r][1] = fma2_(w2.y, px, acc[r][1]);
            px = pack2_(xq.w); acc[r][0] = fma2_(w3.x, px, acc[r][0]); acc[r][1] = fma2_(w3.y, px, acc[r][1]);
        }
    }
#pragma unroll
    for (int r = 0; r < 32; r++) {
        ulonglong2 o2; o2.x = acc[r][0]; o2.y = acc[r][1];
        *reinterpret_cast<ulonglong2*>(out + (size_t)(rt * 32 + r) * V + vv) = o2;
    }
}

// ---------------- launch -------------------------------------------------------
extern "C" void kernel_launch(void* const* d_in, const int* in_sizes, int n_in,
                              void* d_out, int out_size) {
    (void)in_sizes; (void)n_in; (void)out_size;
    const int*   idx      = (const int*)  d_in[0];
    const float* tok_emb  = (const float*)d_in[1];
    const float* pe_tab   = (const float*)d_in[2];
    const float* pe_W1    = (const float*)d_in[3];
    const float* pe_b1    = (const float*)d_in[4];
    const float* pe_W2    = (const float*)d_in[5];
    const float* pe_b2    = (const float*)d_in[6];
    const float* pe_lg    = (const float*)d_in[7];
    const float* pe_lb    = (const float*)d_in[8];
    const float* ln1_g    = (const float*)d_in[9];
    const float* ln1_b    = (const float*)d_in[10];
    const float* att_W1   = (const float*)d_in[11];
    const float* att_b1   = (const float*)d_in[12];
    const float* att_W2   = (const float*)d_in[13];
    /* att_b2 = d_in[14] — constant over j, cancels in softmax */
    const float* val_W    = (const float*)d_in[15];
    const float* proj_W   = (const float*)d_in[16];
    const float* proj_b   = (const float*)d_in[17];
    const float* ln2_g    = (const float*)d_in[18];
    const float* ln2_b    = (const float*)d_in[19];
    const float* ff_W1    = (const float*)d_in[20];
    const float* ff_b1    = (const float*)d_in[21];
    const float* ff_W2    = (const float*)d_in[22];
    const float* ff_b2    = (const float*)d_in[23];
    const float* ln3_g    = (const float*)d_in[24];
    const float* ln3_b    = (const float*)d_in[25];
    const float* lm_W     = (const float*)d_in[26];
    const float* lm_b     = (const float*)d_in[27];
    float* out = (float*)d_out;

    k_pos<<<dim3(NPE, T), 64>>>(pe_tab, pe_W1, pe_b1, pe_W2, pe_b2, pe_lg, pe_lb);
    k_embln<<<BT, 64>>>(idx, tok_emb, ln1_g, ln1_b, val_W);
    for (int p = 0; p < NPE; p++) {
        k_qk  <<<dim3(T / 16, H * B, 4), 64>>>(att_W1, att_b1, p);
        k_attn<<<dim3(T, H * B), 256>>>(att_W2);
        k_mlp <<<BT / 2, 64>>>(proj_W, proj_b, ln2_g, ln2_b,
                               ff_W1, ff_b1, ff_W2, ff_b2, ln3_g, ln3_b,
                               ln1_g, ln1_b, val_W);
    }
    k_lm<<<dim3(V / 256, BT / 32), 64>>>(lm_W, lm_b, out);
}

// round 10
// speedup vs baseline: 1.1484x; 1.0233x over previous
#include <cuda_runtime.h>
#include <cuda_fp16.h>

#define DINL __device__ __forceinline__
typedef unsigned long long ull;
typedef unsigned int uint;
#define FULLM 0xffffffffu

constexpr int V   = 32000;
constexpr int C   = 64;
constexpr int H   = 4;
constexpr int S   = 16;
constexpr int T   = 128;
constexpr int B   = 2;
constexpr int HID = 256;
constexpr int NPE = 4;
constexpr int BT  = B * T;     // 256
constexpr int D4  = 4 * C;     // 256

// ---------------- scratch (device globals; no malloc allowed) ----------------
__device__ float   g_x   [BT * C];
__device__ float   g_xn  [BT * C];
__device__ float   g_pos [NPE * T * C];
__device__ __half2 g_Qh2 [H * B * T * 128];   // [hb][t][dp], dp = d/2 pairs
__device__ __half2 g_Kh2 [H * B * 128 * T];   // [hb][dp][t]
__device__ float   g_vbuf[2][H * B * T * S];  // double-buffered v

DINL float sigmoidf_(float x) { return 1.0f / (1.0f + __expf(-x)); }

// packed f32x2 helpers (Blackwell: fma.rn.f32x2)
DINL ull fma2_(ull a, ull b, ull c) {
    ull r;
    asm("fma.rn.f32x2 %0, %1, %2, %3;" : "=l"(r) : "l"(a), "l"(b), "l"(c));
    return r;
}
DINL ull pack2_(float v) {
    ull r; unsigned u = __float_as_uint(v);
    asm("mov.b64 %0, {%1, %2};" : "=l"(r) : "r"(u), "r"(u));
    return r;
}
DINL ull packlh_(float lo, float hi) {
    ull r;
    asm("mov.b64 %0, {%1, %2};" : "=l"(r) : "r"(__float_as_uint(lo)), "r"(__float_as_uint(hi)));
    return r;
}
DINL void unpack2_(ull v, float& lo, float& hi) {
    unsigned a, b;
    asm("mov.b64 {%0, %1}, %2;" : "=r"(a), "=r"(b) : "l"(v));
    lo = __uint_as_float(a); hi = __uint_as_float(b);
}
DINL float wsum32_(float v) {
#pragma unroll
    for (int off = 16; off; off >>= 1) v += __shfl_xor_sync(FULLM, v, off);
    return v;
}
DINL uint tanh2_(uint x) {
    asm("tanh.approx.f16x2 %0, %1;" : "=r"(x) : "r"(x));
    return x;
}
DINL __half2 u2h_(uint u) { __half2 h; *reinterpret_cast<uint*>(&h) = u; return h; }
DINL uint h2u_(__half2 h) { return *reinterpret_cast<uint*>(&h); }

// block-wide sum over exactly 64 threads
DINL float bsum64(float v, float* sb, int tid) {
    sb[tid] = v; __syncthreads();
#pragma unroll
    for (int off = 32; off; off >>= 1) {
        if (tid < off) sb[tid] += sb[tid + off];
        __syncthreads();
    }
    float r = sb[0]; __syncthreads();
    return r;
}

// ---------------- K0: positional embeddings (4 tables, table->FFN->LN) -------
__global__ void k_pos(const float* __restrict__ tab,
                      const float* __restrict__ W1, const float* __restrict__ b1,
                      const float* __restrict__ W2, const float* __restrict__ b2,
                      const float* __restrict__ lg, const float* __restrict__ lb) {
    int p = blockIdx.x, t = blockIdx.y, c = threadIdx.x;
    __shared__ float pe[64], hh[64], sb[64];
    pe[c] = tab[(p * T + t) * C + c];
    __syncthreads();
    float a = b1[p * C + c];
    const float* w1 = W1 + p * C * C;
#pragma unroll 8
    for (int k = 0; k < C; k++) a = fmaf(pe[k], w1[k * C + c], a);
    hh[c] = sigmoidf_(a);
    __syncthreads();
    float y = b2[p * C + c];
    const float* w2 = W2 + p * C * C;
#pragma unroll 8
    for (int k = 0; k < C; k++) y = fmaf(hh[k], w2[k * C + c], y);
    float m = bsum64(y, sb, c) * (1.f / C);
    float d = y - m;
    float var = bsum64(d * d, sb, c) * (1.f / C);
    g_pos[(p * T + t) * C + c] = d * rsqrtf(var + 1e-5f) * lg[p * C + c] + lb[p * C + c];
}

// ---------------- K1: embed gather + ln1 + v projection (first iter only) ----
__global__ void k_embln(const int* __restrict__ idxp, const float* __restrict__ tok,
                        const float* __restrict__ g1, const float* __restrict__ b1,
                        const float* __restrict__ valW) {
    int row = blockIdx.x, c = threadIdx.x;
    int b = row >> 7, t = row & 127;
    __shared__ float xs[64], sb[64];
    float x = tok[idxp[row] * C + c];
    g_x[row * C + c] = x;
    float m = bsum64(x, sb, c) * (1.f / C);
    float d = x - m;
    float var = bsum64(d * d, sb, c) * (1.f / C);
    float xn = d * rsqrtf(var + 1e-5f) * g1[c] + b1[c];
    g_xn[row * C + c] = xn;
    xs[c] = xn;
    __syncthreads();
    int h = c >> 4, s = c & 15;
    float a = 0.f;
    const float* w = valW + h * C * S + s;
#pragma unroll 8
    for (int k = 0; k < C; k++) a = fmaf(xs[k], w[k * S], a);
    g_vbuf[0][((h * B + b) * T + t) * S + s] = a;
}

// ---------------- K2: Q/K projections -> half2 d-pairs ------------------------
// grid (T/16, H*B, 4 d-quarters), block 64 (one thread per d within quarter)
__global__ void __launch_bounds__(64) k_qk(const float* __restrict__ W1,
                                           const float* __restrict__ b1, int p) {
    int dq = blockIdx.z;
    int hb = blockIdx.y;
    int h = hb >> 1, b = hb & 1;
    int t0 = blockIdx.x * 16;
    int tid = threadIdx.x;              // 0..63
    int d = dq * 64 + tid;

    __shared__ float xs[128][18];       // [c][tt], 16 tokens, 8B-aligned rows

    for (int idx = tid; idx < 128 * 16; idx += 64) {
        int c = idx & 127, tt = idx >> 7;
        xs[c][tt] = (c < 64) ? g_pos[(p * T + t0 + tt) * C + c]
                             : g_xn[(b * T + t0 + tt) * C + (c - 64)];
    }
    __syncthreads();

    ull ak2[8], aq2[8];
    ull bq2 = pack2_(0.5f * b1[h * D4 + d]);
#pragma unroll
    for (int u = 0; u < 8; u++) { ak2[u] = 0ULL; aq2[u] = bq2; }

    const float* Wk = W1 + h * D4 * D4 + d;   // rows [0,128): key half
    const float* Wq = Wk + 128 * D4;          // rows [128,256): query half

    for (int c0 = 0; c0 < 128; c0 += 16) {
        float wk[16], wq[16];
#pragma unroll
        for (int u = 0; u < 16; u++) {
            wk[u] = Wk[(c0 + u) * D4];
            wq[u] = Wq[(c0 + u) * D4];
        }
#pragma unroll
        for (int cc = 0; cc < 16; cc++) {
            ull wk2 = pack2_(0.5f * wk[cc]);
            ull wq2 = pack2_(0.5f * wq[cc]);
            const ull* xp = reinterpret_cast<const ull*>(&xs[c0 + cc][0]);
#pragma unroll
            for (int u = 0; u < 8; u++) {
                ull xv = xp[u];
                ak2[u] = fma2_(xv, wk2, ak2[u]);
                aq2[u] = fma2_(xv, wq2, aq2[u]);
            }
        }
    }

    // pair neighbor dims (d even, d+1) via shfl; even lanes store half2
    int dp = d >> 1;
    bool even = !(tid & 1);
    __half2* Kb = g_Kh2 + (size_t)(hb * 128 + dp) * T + t0;
#pragma unroll
    for (int u = 0; u < 8; u++) {
        float klo, khi, qlo, qhi;
        unpack2_(ak2[u], klo, khi);
        unpack2_(aq2[u], qlo, qhi);
        float nklo = __shfl_xor_sync(FULLM, klo, 1);
        float nkhi = __shfl_xor_sync(FULLM, khi, 1);
        float nqlo = __shfl_xor_sync(FULLM, qlo, 1);
        float nqhi = __shfl_xor_sync(FULLM, qhi, 1);
        if (even) {
            Kb[2 * u]     = __floats2half2_rn(klo, nklo);
            Kb[2 * u + 1] = __floats2half2_rn(khi, nkhi);
            g_Qh2[(size_t)(hb * T + t0 + 2 * u) * 128 + dp]     = __floats2half2_rn(qlo, nqlo);
            g_Qh2[(size_t)(hb * T + t0 + 2 * u + 1) * 128 + dp] = __floats2half2_rn(qhi, nqhi);
        }
    }
}

// ---------------- K3: fused attention (f16x2 tanh) + MLP, paired tokens -------
// grid 128 blocks, 512 threads. Block bk: tokenA (b=0,i=bk), tokenB (b=1,i=127-bk).
__global__ void __launch_bounds__(512) k_attnmlp(
        const float* __restrict__ W2a, int vsel,
        const float* __restrict__ pW, const float* __restrict__ pb,
        const float* __restrict__ g2, const float* __restrict__ b2,
        const float* __restrict__ fW1, const float* __restrict__ fb1,
        const float* __restrict__ fW2, const float* __restrict__ fb2,
        const float* __restrict__ g3, const float* __restrict__ b3,
        const float* __restrict__ g1, const float* __restrict__ b1,
        const float* __restrict__ valW) {
    int bk = blockIdx.x;
    int tid = threadIdx.x;
    const float* vcur = g_vbuf[vsel];
    float* vnext = g_vbuf[vsel ^ 1];

    __shared__ uint2 qws[2][4][128];   // {q half2, 0.5*W2 half2} per (token, head, dpair)
    __shared__ float scf[2][4][128];   // scores -> wei
    __shared__ float opart[4][128];
    __shared__ float osm2[2][64];
    __shared__ ull   hs2m[2][256];

    // stage Q (half2) + W2 (half2)
    for (int idx = tid; idx < 1024; idx += 512) {
        int tk = idx >> 9, hh = (idx >> 7) & 3, dp = idx & 127;
        int i_tk = tk ? (127 - bk) : bk;
        __half2 qh = g_Qh2[(size_t)((hh * B + tk) * T + i_tk) * 128 + dp];
        uint2 e;
        e.x = h2u_(qh);
        e.y = h2u_(__floats2half2_rn(0.5f * W2a[hh * D4 + 2 * dp],
                                     0.5f * W2a[hh * D4 + 2 * dp + 1]));
        qws[tk][hh][dp] = e;
    }
    __syncthreads();

    // scores: tid = h*128 + jr; j bit-interleaved for warp balance
    {
        int jr = tid & 127, hh = tid >> 7;
        int j = ((jr & 3) << 5) | (jr >> 2);
        for (int tk = 0; tk < 2; tk++) {
            int i_tk = tk ? (127 - bk) : bk;
            float acc = 0.f;
            if (j <= i_tk) {
                const __half2* Kc = g_Kh2 + (size_t)((hh * B + tk) * 128) * T + j;
                const uint2* qp = &qws[tk][hh][0];
                for (int dp0 = 0; dp0 < 128; dp0 += 16) {
                    uint kb[16];
#pragma unroll
                    for (int u = 0; u < 16; u++)
                        kb[u] = h2u_(Kc[(dp0 + u) * T]);
                    uint hacc = 0;
#pragma unroll
                    for (int u = 0; u < 16; u++) {
                        uint2 qw = qp[dp0 + u];
                        uint tv = h2u_(__hadd2(u2h_(qw.x), u2h_(kb[u])));
                        tv = tanh2_(tv);
                        hacc = h2u_(__hfma2(u2h_(qw.y), u2h_(tv), u2h_(hacc)));
                    }
                    float2 f2 = __half22float2(u2h_(hacc));
                    acc += f2.x + f2.y;
                }
            }
            scf[tk][hh][j] = (j <= i_tk) ? acc * 0.125f : -1e30f;
        }
    }
    __syncthreads();

    // softmax: warp w handles (tk = w>>2, h = w&3)
    int wid = tid >> 5, lane = tid & 31;
    if (wid < 8) {
        float* row = &scf[wid >> 2][wid & 3][0];
        float v0 = row[lane], v1 = row[lane + 32], v2 = row[lane + 64], v3 = row[lane + 96];
        float mx = fmaxf(fmaxf(v0, v1), fmaxf(v2, v3));
#pragma unroll
        for (int off = 16; off; off >>= 1) mx = fmaxf(mx, __shfl_xor_sync(FULLM, mx, off));
        float e0 = __expf(v0 - mx), e1 = __expf(v1 - mx);
        float e2 = __expf(v2 - mx), e3 = __expf(v3 - mx);
        float s = e0 + e1 + e2 + e3;
#pragma unroll
        for (int off = 16; off; off >>= 1) s += __shfl_xor_sync(FULLM, s, off);
        float inv = __fdividef(1.f, s);
        row[lane] = e0 * inv; row[lane + 32] = e1 * inv;
        row[lane + 64] = e2 * inv; row[lane + 96] = e3 * inv;
    }
    __syncthreads();

    // o: thread (part, out): out -> (tk, h, s); sum j = part + 4k
    {
        int part = tid >> 7, out = tid & 127;
        int tk = out >> 6, hs = out & 63, hh = hs >> 4, s = hs & 15;
        int i_tk = tk ? (127 - bk) : bk;
        const float* vp = vcur + ((hh * B + tk) * T) * S + s;
        float a = 0.f;
        for (int jj = part; jj <= i_tk; jj += 4)
            a = fmaf(scf[tk][hh][jj], vp[jj * S], a);
        opart[part][out] = a;
    }
    __syncthreads();
    if (tid < 128) {
        int tk = tid >> 6, hs = tid & 63;
        osm2[tk][hs] = opart[0][tid] + opart[1][tid] + opart[2][tid] + opart[3][tid];
    }
    __syncthreads();

    // ---- phase B: MLP for the two rows, warps 0 and 1 ----
    if (wid < 2) {
        int w = wid, lam = lane;
        int b = w, t = w ? (127 - bk) : bk;
        int row = b * T + t;

        float2 o2 = make_float2(osm2[w][2 * lam], osm2[w][2 * lam + 1]);
        float2 x2 = reinterpret_cast<const float2*>(g_x)[row * 32 + lam];
        float2 pb2 = reinterpret_cast<const float2*>(pb)[lam];

        ull acc = packlh_(x2.x + pb2.x, x2.y + pb2.y);
        const ull* pW2 = reinterpret_cast<const ull*>(pW);
#pragma unroll 4
        for (int kp = 0; kp < 32; kp++) {
            float ox = __shfl_sync(FULLM, o2.x, kp);
            float oy = __shfl_sync(FULLM, o2.y, kp);
            ull w0 = pW2[(2 * kp) * 32 + lam];
            ull w1 = pW2[(2 * kp + 1) * 32 + lam];
            acc = fma2_(pack2_(ox), w0, acc);
            acc = fma2_(pack2_(oy), w1, acc);
        }
        float xv0, xv1; unpack2_(acc, xv0, xv1);

        float m = wsum32_(xv0 + xv1) * (1.f / C);
        float d0 = xv0 - m, d1 = xv1 - m;
        float var = wsum32_(d0 * d0 + d1 * d1) * (1.f / C);
        float rstd = rsqrtf(var + 1e-5f);
        float2 g2v = reinterpret_cast<const float2*>(g2)[lam];
        float2 b2v = reinterpret_cast<const float2*>(b2)[lam];
        float xn0 = d0 * rstd * g2v.x + b2v.x;
        float xn1 = d1 * rstd * g2v.y + b2v.y;

        ull a4[4];
        const ull* fb1u = reinterpret_cast<const ull*>(fb1);
#pragma unroll
        for (int u = 0; u < 4; u++) a4[u] = fb1u[lam * 4 + u];
#pragma unroll 4
        for (int kp = 0; kp < 32; kp++) {
            float k0v = __shfl_sync(FULLM, xn0, kp);
            float k1v = __shfl_sync(FULLM, xn1, kp);
            const ull* r0 = reinterpret_cast<const ull*>(fW1 + (2 * kp) * HID) + lam * 4;
            const ull* r1 = r0 + HID / 2;
            ull p0 = pack2_(k0v), p1 = pack2_(k1v);
#pragma unroll
            for (int u = 0; u < 4; u++) {
                a4[u] = fma2_(p0, r0[u], a4[u]);
                a4[u] = fma2_(p1, r1[u], a4[u]);
            }
        }
#pragma unroll
        for (int u = 0; u < 4; u++) {
            float lo, hi; unpack2_(a4[u], lo, hi);
            hs2m[w][8 * lam + 2 * u]     = pack2_(sigmoidf_(lo));
            hs2m[w][8 * lam + 2 * u + 1] = pack2_(sigmoidf_(hi));
        }
        __syncwarp();

        float2 fb2v = reinterpret_cast<const float2*>(fb2)[lam];
        ull accy = packlh_(xv0 + fb2v.x, xv1 + fb2v.y);
        const ull* fW2u = reinterpret_cast<const ull*>(fW2);
#pragma unroll 8
        for (int k = 0; k < HID; k++)
            accy = fma2_(hs2m[w][k], fW2u[k * 32 + lam], accy);
        float y0, y1; unpack2_(accy, y0, y1);

        m = wsum32_(y0 + y1) * (1.f / C);
        d0 = y0 - m; d1 = y1 - m;
        var = wsum32_(d0 * d0 + d1 * d1) * (1.f / C);
        rstd = rsqrtf(var + 1e-5f);
        float2 g3v = reinterpret_cast<const float2*>(g3)[lam];
        float2 b3v = reinterpret_cast<const float2*>(b3)[lam];
        float z0 = d0 * rstd * g3v.x + b3v.x;
        float z1 = d1 * rstd * g3v.y + b3v.y;
        reinterpret_cast<float2*>(g_x)[row * 32 + lam] = make_float2(z0, z1);

        // ln1 for next layer
        m = wsum32_(z0 + z1) * (1.f / C);
        d0 = z0 - m; d1 = z1 - m;
        var = wsum32_(d0 * d0 + d1 * d1) * (1.f / C);
        rstd = rsqrtf(var + 1e-5f);
        float2 g1v = reinterpret_cast<const float2*>(g1)[lam];
        float2 b1v = reinterpret_cast<const float2*>(b1)[lam];
        float q0 = d0 * rstd * g1v.x + b1v.x;
        float q1 = d1 * rstd * g1v.y + b1v.y;
        reinterpret_cast<float2*>(g_xn)[row * 32 + lam] = make_float2(q0, q1);

        // v projection for next layer (into the other buffer)
        int hv = lam >> 3, sp = lam & 7;
        const ull* vwb = reinterpret_cast<const ull*>(valW) + hv * 512 + sp;
        ull accv = 0ULL;
#pragma unroll 4
        for (int kp = 0; kp < 32; kp++) {
            float k0v = __shfl_sync(FULLM, q0, kp);
            float k1v = __shfl_sync(FULLM, q1, kp);
            ull w0 = vwb[kp * 16];
            ull w1 = vwb[kp * 16 + 8];
            accv = fma2_(pack2_(k0v), w0, accv);
            accv = fma2_(pack2_(k1v), w1, accv);
        }
        reinterpret_cast<ull*>(vnext)[((hv * B + b) * T + t) * 8 + sp] = accv;
    }
}

// ---------------- K5: lm_head, 4 vocab/thread, f32x2 --------------------------
__global__ void __launch_bounds__(64) k_lm(const float* __restrict__ W,
                                           const float* __restrict__ bias,
                                           float* __restrict__ out) {
    int vt = blockIdx.x, rt = blockIdx.y;
    int vv = vt * 256 + threadIdx.x * 4;
    __shared__ alignas(16) float xs[32][68];
    for (int idx = threadIdx.x; idx < 32 * 64; idx += 64) {
        int r = idx >> 6, cc = idx & 63;
        xs[r][cc] = g_x[(rt * 32 + r) * C + cc];
    }
    ulonglong2 bb = *reinterpret_cast<const ulonglong2*>(bias + vv);
    ull acc[32][2];
#pragma unroll
    for (int r = 0; r < 32; r++) { acc[r][0] = bb.x; acc[r][1] = bb.y; }
    __syncthreads();
    for (int cb = 0; cb < 64; cb += 4) {
        const ulonglong2 w0 = *reinterpret_cast<const ulonglong2*>(W + (size_t)(cb + 0) * V + vv);
        const ulonglong2 w1 = *reinterpret_cast<const ulonglong2*>(W + (size_t)(cb + 1) * V + vv);
        const ulonglong2 w2 = *reinterpret_cast<const ulonglong2*>(W + (size_t)(cb + 2) * V + vv);
        const ulonglong2 w3 = *reinterpret_cast<const ulonglong2*>(W + (size_t)(cb + 3) * V + vv);
#pragma unroll
        for (int r = 0; r < 32; r++) {
            const float4 xq = *reinterpret_cast<const float4*>(&xs[r][cb]);
            ull px;
            px = pack2_(xq.x); acc[r][0] = fma2_(w0.x, px, acc[r][0]); acc[r][1] = fma2_(w0.y, px, acc[r][1]);
            px = pack2_(xq.y); acc[r][0] = fma2_(w1.x, px, acc[r][0]); acc[r][1] = fma2_(w1.y, px, acc[r][1]);
            px = pack2_(xq.z); acc[r][0] = fma2_(w2.x, px, acc[r][0]); acc[r][1] = fma2_(w2.y, px, acc[r][1]);
            px = pack2_(xq.w); acc[r][0] = fma2_(w3.x, px, acc[r][0]); acc[r][1] = fma2_(w3.y, px, acc[r][1]);
        }
    }
#pragma unroll
    for (int r = 0; r < 32; r++) {
        ulonglong2 o2; o2.x = acc[r][0]; o2.y = acc[r][1];
        *reinterpret_cast<ulonglong2*>(out + (size_t)(rt * 32 + r) * V + vv) = o2;
    }
}

// ---------------- launch -------------------------------------------------------
extern "C" void kernel_launch(void* const* d_in, const int* in_sizes, int n_in,
                              void* d_out, int out_size) {
    (void)in_sizes; (void)n_in; (void)out_size;
    const int*   idx      = (const int*)  d_in[0];
    const float* tok_emb  = (const float*)d_in[1];
    const float* pe_tab   = (const float*)d_in[2];
    const float* pe_W1    = (const float*)d_in[3];
    const float* pe_b1    = (const float*)d_in[4];
    const float* pe_W2    = (const float*)d_in[5];
    const float* pe_b2    = (const float*)d_in[6];
    const float* pe_lg    = (const float*)d_in[7];
    const float* pe_lb    = (const float*)d_in[8];
    const float* ln1_g    = (const float*)d_in[9];
    const float* ln1_b    = (const float*)d_in[10];
    const float* att_W1   = (const float*)d_in[11];
    const float* att_b1   = (const float*)d_in[12];
    const float* att_W2   = (const float*)d_in[13];
    /* att_b2 = d_in[14] — constant over j, cancels in softmax */
    const float* val_W    = (const float*)d_in[15];
    const float* proj_W   = (const float*)d_in[16];
    const float* proj_b   = (const float*)d_in[17];
    const float* ln2_g    = (const float*)d_in[18];
    const float* ln2_b    = (const float*)d_in[19];
    const float* ff_W1    = (const float*)d_in[20];
    const float* ff_b1    = (const float*)d_in[21];
    const float* ff_W2    = (const float*)d_in[22];
    const float* ff_b2    = (const float*)d_in[23];
    const float* ln3_g    = (const float*)d_in[24];
    const float* ln3_b    = (const float*)d_in[25];
    const float* lm_W     = (const float*)d_in[26];
    const float* lm_b     = (const float*)d_in[27];
    float* out = (float*)d_out;

    k_pos<<<dim3(NPE, T), 64>>>(pe_tab, pe_W1, pe_b1, pe_W2, pe_b2, pe_lg, pe_lb);
    k_embln<<<BT, 64>>>(idx, tok_emb, ln1_g, ln1_b, val_W);
    for (int p = 0; p < NPE; p++) {
        k_qk<<<dim3(T / 16, H * B, 4), 64>>>(att_W1, att_b1, p);
        k_attnmlp<<<128, 512>>>(att_W2, p & 1,
                                proj_W, proj_b, ln2_g, ln2_b,
                                ff_W1, ff_b1, ff_W2, ff_b2, ln3_g, ln3_b,
                                ln1_g, ln1_b, val_W);
    }
    k_lm<<<dim3(V / 256, BT / 32), 64>>>(lm_W, lm_b, out);
}